// round 15
// baseline (speedup 1.0000x reference)
#include <cuda_runtime.h>
#include <cuda_bf16.h>
#include <cstdint>
#include <math.h>

// Problem constants (fixed by the reference)
#define NB      8
#define LQ      4096
#define DMODEL  256
#define MHEADS  8
#define PPTS    4
#define DH      32
#define HDIM    64
#define WDIM    64
#define NROWS   (NB * LQ)          // 32768
#define NHW     (HDIM * WDIM)      // 4096

// ---------------------------------------------------------------------------
// Scratch (device globals; no runtime allocation allowed)
// ---------------------------------------------------------------------------
__device__ float  g_value[NB * NHW * DMODEL];         // 33.5 MB
__device__ float  g_samp [NROWS * DMODEL];            // 33.5 MB
__device__ float4 g_pts  [NROWS * MHEADS * PPTS];     // (x, y, attw, pad) 16.8 MB
__device__ __nv_bfloat16 g_wv_hi[DMODEL * DMODEL];
__device__ __nv_bfloat16 g_wv_lo[DMODEL * DMODEL];
__device__ __nv_bfloat16 g_wo_hi[DMODEL * DMODEL];
__device__ __nv_bfloat16 g_wo_lo[DMODEL * DMODEL];

// ---------------------------------------------------------------------------
// Warp-MMA helpers (sm_80-class PTX; legal on plain sm_100)
// ---------------------------------------------------------------------------
__device__ __forceinline__ uint32_t smem_u32(const void* p) {
    uint32_t a;
    asm("{ .reg .u64 t; cvta.to.shared.u64 t, %1; cvt.u32.u64 %0, t; }"
        : "=r"(a) : "l"(p));
    return a;
}

__device__ __forceinline__ void ldsm4(uint32_t& a, uint32_t& b, uint32_t& c,
                                      uint32_t& d, uint32_t addr) {
    asm volatile("ldmatrix.sync.aligned.m8n8.x4.shared.b16 {%0,%1,%2,%3}, [%4];"
                 : "=r"(a), "=r"(b), "=r"(c), "=r"(d) : "r"(addr));
}

__device__ __forceinline__ void mma_bf16(float* c, const uint32_t* a,
                                         uint32_t b0, uint32_t b1) {
    asm volatile(
        "mma.sync.aligned.m16n8k16.row.col.f32.bf16.bf16.f32 "
        "{%0,%1,%2,%3}, {%4,%5,%6,%7}, {%8,%9}, {%0,%1,%2,%3};"
        : "+f"(c[0]), "+f"(c[1]), "+f"(c[2]), "+f"(c[3])
        : "r"(a[0]), "r"(a[1]), "r"(a[2]), "r"(a[3]), "r"(b0), "r"(b1));
}

// ---------------------------------------------------------------------------
// Weight split: W -> (hi, lo) bf16 pair for both Wv and Wo.
// ---------------------------------------------------------------------------
__global__ __launch_bounds__(256) void conv_weights_kernel(
    const float* __restrict__ Wv, const float* __restrict__ Wo)
{
    const int i = blockIdx.x * 256 + threadIdx.x;
    const int NN = DMODEL * DMODEL;
    float v = (i < NN) ? Wv[i] : Wo[i - NN];
    __nv_bfloat16 h = __float2bfloat16(v);
    __nv_bfloat16 l = __float2bfloat16(v - __bfloat162float(h));
    if (i < NN) { g_wv_hi[i] = h; g_wv_lo[i] = l; }
    else        { g_wo_hi[i - NN] = h; g_wo_lo[i - NN] = l; }
}

// ---------------------------------------------------------------------------
// HMMA split-bf16 GEMM (byte-identical to the R13 winner).
// Block 128x128, BK=32, 8 warps, __launch_bounds__(256,2) -> 2 CTAs/SM.
// ---------------------------------------------------------------------------
#define BK   32
#define SPAD 40   // bf16 per smem row (80 B; 16B-aligned, conflict-free)

template <int SEL>
__global__ __launch_bounds__(256, 2) void mma_gemm_kernel(
    const float* __restrict__ Aext, const float* __restrict__ bias,
    float* __restrict__ Cext)
{
    __shared__ __nv_bfloat16 Ah[128][SPAD];
    __shared__ __nv_bfloat16 Al[128][SPAD];
    __shared__ __nv_bfloat16 Bh[128][SPAD];
    __shared__ __nv_bfloat16 Bl[128][SPAD];

    const float* A = (SEL == 0) ? Aext : g_samp;
    float*       C = (SEL == 0) ? g_value : Cext;
    const __nv_bfloat16* Wh = (SEL == 0) ? g_wv_hi : g_wo_hi;
    const __nv_bfloat16* Wl = (SEL == 0) ? g_wv_lo : g_wo_lo;

    const int tid  = threadIdx.x;
    const int wid  = tid >> 5;
    const int lane = tid & 31;
    const int m0   = blockIdx.x * 128;
    const int n0   = blockIdx.y * 128;

    const int wm = wid >> 1;
    const int wn = wid & 1;

    const int lrow = tid >> 1;
    const int lkb  = (tid & 1) * 16;

    const float*         Ap  = A  + (size_t)(m0 + lrow) * DMODEL + lkb;
    const __nv_bfloat16* Whp = Wh + (size_t)(n0 + lrow) * DMODEL + lkb;
    const __nv_bfloat16* Wlp = Wl + (size_t)(n0 + lrow) * DMODEL + lkb;

    const int a_row = (lane & 15);
    const int a_k   = (lane >> 4) * 8;
    const int b_g   = lane >> 3;
    const int b_row = (b_g >> 1) * 8 + (lane & 7);
    const int b_k   = (b_g & 1) * 8;

    const uint32_t ah_b = smem_u32(Ah);
    const uint32_t al_b = smem_u32(Al);
    const uint32_t bh_b = smem_u32(Bh);
    const uint32_t bl_b = smem_u32(Bl);

    float acc[2][8][4];
#pragma unroll
    for (int i = 0; i < 2; i++)
#pragma unroll
        for (int j = 0; j < 8; j++)
#pragma unroll
            for (int k = 0; k < 4; k++) acc[i][j][k] = 0.0f;

    for (int k0 = 0; k0 < DMODEL; k0 += BK) {
        if (k0) __syncthreads();

        uint32_t* ah = reinterpret_cast<uint32_t*>(&Ah[lrow][lkb]);
        uint32_t* al = reinterpret_cast<uint32_t*>(&Al[lrow][lkb]);
#pragma unroll
        for (int c = 0; c < 4; c++) {
            float4 v = *reinterpret_cast<const float4*>(Ap + k0 + c * 4);
            __nv_bfloat162 h0 = __floats2bfloat162_rn(v.x, v.y);
            __nv_bfloat162 h1 = __floats2bfloat162_rn(v.z, v.w);
            float2 f0 = __bfloat1622float2(h0);
            float2 f1 = __bfloat1622float2(h1);
            __nv_bfloat162 l0 = __floats2bfloat162_rn(v.x - f0.x, v.y - f0.y);
            __nv_bfloat162 l1 = __floats2bfloat162_rn(v.z - f1.x, v.w - f1.y);
            ah[c * 2 + 0] = *reinterpret_cast<uint32_t*>(&h0);
            ah[c * 2 + 1] = *reinterpret_cast<uint32_t*>(&h1);
            al[c * 2 + 0] = *reinterpret_cast<uint32_t*>(&l0);
            al[c * 2 + 1] = *reinterpret_cast<uint32_t*>(&l1);
        }
        *reinterpret_cast<uint4*>(&Bh[lrow][lkb]) =
            *reinterpret_cast<const uint4*>(Whp + k0);
        *reinterpret_cast<uint4*>(&Bh[lrow][lkb + 8]) =
            *reinterpret_cast<const uint4*>(Whp + k0 + 8);
        *reinterpret_cast<uint4*>(&Bl[lrow][lkb]) =
            *reinterpret_cast<const uint4*>(Wlp + k0);
        *reinterpret_cast<uint4*>(&Bl[lrow][lkb + 8]) =
            *reinterpret_cast<const uint4*>(Wlp + k0 + 8);
        __syncthreads();

#pragma unroll
        for (int ks = 0; ks < 2; ks++) {
            uint32_t ahi[2][4], alo[2][4];
#pragma unroll
            for (int mt = 0; mt < 2; mt++) {
                uint32_t off = ((wm * 32 + mt * 16 + a_row) * SPAD
                                + ks * 16 + a_k) * 2;
                ldsm4(ahi[mt][0], ahi[mt][1], ahi[mt][2], ahi[mt][3], ah_b + off);
                ldsm4(alo[mt][0], alo[mt][1], alo[mt][2], alo[mt][3], al_b + off);
            }
#pragma unroll
            for (int ntp = 0; ntp < 4; ntp++) {
                uint32_t off = ((wn * 64 + ntp * 16 + b_row) * SPAD
                                + ks * 16 + b_k) * 2;
                uint32_t bh0, bh1, bh2, bh3, bl0, bl1, bl2, bl3;
                ldsm4(bh0, bh1, bh2, bh3, bh_b + off);
                ldsm4(bl0, bl1, bl2, bl3, bl_b + off);
#pragma unroll
                for (int mt = 0; mt < 2; mt++) {
                    mma_bf16(acc[mt][ntp * 2 + 0], ahi[mt], bh0, bh1);
                    mma_bf16(acc[mt][ntp * 2 + 1], ahi[mt], bh2, bh3);
                }
#pragma unroll
                for (int mt = 0; mt < 2; mt++) {
                    mma_bf16(acc[mt][ntp * 2 + 0], alo[mt], bh0, bh1);
                    mma_bf16(acc[mt][ntp * 2 + 1], alo[mt], bh2, bh3);
                }
#pragma unroll
                for (int mt = 0; mt < 2; mt++) {
                    mma_bf16(acc[mt][ntp * 2 + 0], ahi[mt], bl0, bl1);
                    mma_bf16(acc[mt][ntp * 2 + 1], ahi[mt], bl2, bl3);
                }
            }
        }
    }

    const int q  = lane >> 2;
    const int rp = (lane & 3) * 2;
#pragma unroll
    for (int mt = 0; mt < 2; mt++) {
        const int r0 = m0 + wm * 32 + mt * 16 + q;
#pragma unroll
        for (int nt = 0; nt < 8; nt++) {
            const int col = n0 + wn * 64 + nt * 8 + rp;
            const float bx = bias[col], by = bias[col + 1];
            float2 o0 = make_float2(acc[mt][nt][0] + bx, acc[mt][nt][1] + by);
            float2 o1 = make_float2(acc[mt][nt][2] + bx, acc[mt][nt][3] + by);
            *reinterpret_cast<float2*>(C + (size_t)r0 * DMODEL + col) = o0;
            *reinterpret_cast<float2*>(C + (size_t)(r0 + 8) * DMODEL + col) = o1;
        }
    }
}

// ---------------------------------------------------------------------------
// Offsets + attention tiled GEMM (mainloop identical to R13); epilogue
// writes packed float4 g_pts records: (x, y, attw, pad).
// ---------------------------------------------------------------------------
__global__ __launch_bounds__(256) void offset_attn_gemm_kernel(
    const float* __restrict__ query, const float* __restrict__ refpts,
    const float* __restrict__ Woff, const float* __restrict__ boff,
    const float* __restrict__ Wa,   const float* __restrict__ ba)
{
    __shared__ union SMem {
        struct { float As[32][128]; float Bs[32][96]; } mm;  // 28 KB (mainloop)
        float logits[128][33];                               // epilogue overlay
    } sm;
    __shared__ float2 refs[128];

    const int tid = threadIdx.x;
    const int m0  = blockIdx.x * 128;
    const int ty  = tid >> 4;
    const int tx  = tid & 15;
    const int lr  = tid >> 1;            // A row (0..127)
    const int lk  = (tid & 1) * 16;      // k offset within chunk

    if (tid < 128) refs[tid] = reinterpret_cast<const float2*>(refpts)[m0 + tid];

    const int br = tid >> 1;             // B row (0..95) when tid<192
    const float* wrow = (br < 64) ? (Woff + (size_t)br * DMODEL)
                                  : (Wa + (size_t)(br - 64) * DMODEL);

    float acc[8][6];
#pragma unroll
    for (int i = 0; i < 8; i++)
#pragma unroll
        for (int j = 0; j < 6; j++) acc[i][j] = 0.0f;

    for (int k0 = 0; k0 < DMODEL; k0 += 32) {
#pragma unroll
        for (int c = 0; c < 4; c++) {
            float4 a = *reinterpret_cast<const float4*>(
                query + (size_t)(m0 + lr) * DMODEL + k0 + lk + c * 4);
            sm.mm.As[lk + c * 4 + 0][lr] = a.x;
            sm.mm.As[lk + c * 4 + 1][lr] = a.y;
            sm.mm.As[lk + c * 4 + 2][lr] = a.z;
            sm.mm.As[lk + c * 4 + 3][lr] = a.w;
        }
        if (tid < 192) {
#pragma unroll
            for (int c = 0; c < 4; c++) {
                float4 b = *reinterpret_cast<const float4*>(wrow + k0 + lk + c * 4);
                sm.mm.Bs[lk + c * 4 + 0][br] = b.x;
                sm.mm.Bs[lk + c * 4 + 1][br] = b.y;
                sm.mm.Bs[lk + c * 4 + 2][br] = b.z;
                sm.mm.Bs[lk + c * 4 + 3][br] = b.w;
            }
        }
        __syncthreads();

#pragma unroll
        for (int kk = 0; kk < 32; kk++) {
            float4 a0 = *reinterpret_cast<const float4*>(&sm.mm.As[kk][ty * 8]);
            float4 a1 = *reinterpret_cast<const float4*>(&sm.mm.As[kk][ty * 8 + 4]);
            float av[8] = {a0.x, a0.y, a0.z, a0.w, a1.x, a1.y, a1.z, a1.w};
            float bv[6];
#pragma unroll
            for (int j = 0; j < 6; j++) bv[j] = sm.mm.Bs[kk][tx * 6 + j];
#pragma unroll
            for (int i = 0; i < 8; i++)
#pragma unroll
                for (int j = 0; j < 6; j++) acc[i][j] += av[i] * bv[j];
        }
        __syncthreads();
    }

    // Epilogue part 1: offsets -> g_pts.{x,y}; logits -> overlaid smem
    float* ptsf = reinterpret_cast<float*>(g_pts);
#pragma unroll
    for (int i = 0; i < 8; i++) {
        const int row  = ty * 8 + i;
        const int grow = m0 + row;
        const float2 r = refs[row];
#pragma unroll
        for (int j = 0; j < 6; j++) {
            const int c = tx * 6 + j;
            float v = acc[i][j];
            if (c < 64) {
                float refpart = (c & 1) ? r.y * (float)HDIM : r.x * (float)WDIM;
                // record index li = grow*32 + (c>>1); component c&1 (x or y)
                ptsf[((size_t)grow * 32 + (c >> 1)) * 4 + (c & 1)] =
                    v + boff[c] + refpart - 0.5f;
            } else {
                sm.logits[row][c - 64] = v + ba[c - 64];
            }
        }
    }
    __syncthreads();

    // Epilogue part 2: softmax -> g_pts.z
    for (int t = tid; t < 128 * MHEADS; t += 256) {
        const int row = t >> 3;
        const int m   = t & 7;
        float l0 = sm.logits[row][m * 4 + 0];
        float l1 = sm.logits[row][m * 4 + 1];
        float l2 = sm.logits[row][m * 4 + 2];
        float l3 = sm.logits[row][m * 4 + 3];
        float mx = fmaxf(fmaxf(l0, l1), fmaxf(l2, l3));
        float e0 = __expf(l0 - mx), e1 = __expf(l1 - mx);
        float e2 = __expf(l2 - mx), e3 = __expf(l3 - mx);
        float inv = 1.0f / (e0 + e1 + e2 + e3);
        const size_t base = ((size_t)(m0 + row) * 32 + m * 4) * 4;
        ptsf[base + 0 * 4 + 2] = e0 * inv;
        ptsf[base + 1 * 4 + 2] = e1 * inv;
        ptsf[base + 2 * 4 + 2] = e2 * inv;
        ptsf[base + 3 * 4 + 2] = e3 * inv;
    }
}

// ---------------------------------------------------------------------------
// Bilinear sampling + weighted point sum, issue-optimized:
// 1 warp per (row, 4 heads); lane = (head in group) * 8 + channel-quad.
// One LDG.128 per point (packed g_pts); pow2 clamp via &63; unsigned bound
// tests; address = ((y<<6)|x)*DMODEL.
// ---------------------------------------------------------------------------
__global__ __launch_bounds__(256) void sample_kernel()
{
    const int gwid = (blockIdx.x * blockDim.x + threadIdx.x) >> 5;
    const int lane = threadIdx.x & 31;
    const int row  = gwid >> 1;             // n*LQ + lq
    const int mg   = gwid & 1;              // head group (0: m0-3, 1: m4-7)
    const int m    = mg * 4 + (lane >> 3);  // head
    const int cg   = (lane & 7) * 4;        // channel quad within head
    const int n    = row >> 12;             // LQ = 4096

    const float* vbase = g_value + (size_t)(n * NHW) * DMODEL + m * DH + cg;

    float4 acc = make_float4(0.f, 0.f, 0.f, 0.f);
#pragma unroll
    for (int p = 0; p < PPTS; p++) {
        const float4 pt = g_pts[(size_t)row * 32 + m * 4 + p];  // x, y, aw

        float x0f = floorf(pt.x), y0f = floorf(pt.y);
        int   x0  = (int)x0f,     y0  = (int)y0f;
        float wx1 = pt.x - x0f,   wy1 = pt.y - y0f;
        float wx0 = 1.0f - wx1;
        float wy0 = 1.0f - wy1;

        // unsigned bound test folds >=0 && <64 into one compare
        wx0 = ((unsigned)x0       < WDIM) ? wx0 : 0.0f;
        wx1 = ((unsigned)(x0 + 1) < WDIM) ? wx1 : 0.0f;
        wy0 = (((unsigned)y0       < HDIM) ? wy0 : 0.0f) * pt.z;
        wy1 = (((unsigned)(y0 + 1) < HDIM) ? wy1 : 0.0f) * pt.z;

        // pow2 clamp: invalid corners carry zero weight, so any in-range
        // address is fine; & 63 is 1 op and bits are disjoint with y<<6.
        const int x0c = x0 & 63, x1c = (x0 + 1) & 63;
        const int r0 = ((y0 & 63) << 6), r1 = (((y0 + 1) & 63) << 6);

        float4 v00 = *reinterpret_cast<const float4*>(vbase + (r0 | x0c) * DMODEL);
        float4 v01 = *reinterpret_cast<const float4*>(vbase + (r0 | x1c) * DMODEL);
        float4 v10 = *reinterpret_cast<const float4*>(vbase + (r1 | x0c) * DMODEL);
        float4 v11 = *reinterpret_cast<const float4*>(vbase + (r1 | x1c) * DMODEL);

        const float w00 = wy0 * wx0, w01 = wy0 * wx1;
        const float w10 = wy1 * wx0, w11 = wy1 * wx1;
        acc.x += w00 * v00.x + w01 * v01.x + w10 * v10.x + w11 * v11.x;
        acc.y += w00 * v00.y + w01 * v01.y + w10 * v10.y + w11 * v11.y;
        acc.z += w00 * v00.z + w01 * v01.z + w10 * v10.z + w11 * v11.z;
        acc.w += w00 * v00.w + w01 * v01.w + w10 * v10.w + w11 * v11.w;
    }
    *reinterpret_cast<float4*>(g_samp + (size_t)row * DMODEL + m * DH + cg) = acc;
}

// ---------------------------------------------------------------------------
// Launch — kernel launches only.
// ---------------------------------------------------------------------------
extern "C" void kernel_launch(void* const* d_in, const int* in_sizes, int n_in,
                              void* d_out, int out_size)
{
    const float* query = (const float*)d_in[0];
    const float* refp  = (const float*)d_in[1];
    const float* inp   = (const float*)d_in[2];
    // d_in[3] = H, d_in[4] = W (compile-time constants here)
    const float* Wv    = (const float*)d_in[5];
    const float* bv    = (const float*)d_in[6];
    const float* Woff  = (const float*)d_in[7];
    const float* boff  = (const float*)d_in[8];
    const float* Wa    = (const float*)d_in[9];
    const float* ba    = (const float*)d_in[10];
    const float* Wo    = (const float*)d_in[11];
    const float* bo    = (const float*)d_in[12];
    float* out = (float*)d_out;

    dim3 ggrid(NROWS / 128, DMODEL / 128);   // (256, 2)

    // 0) split weights to bf16 hi/lo
    conv_weights_kernel<<<(2 * DMODEL * DMODEL) / 256, 256>>>(Wv, Wo);

    // 1) value = input_flatten @ Wv^T + bv   (HMMA split-bf16, 2 CTAs/SM)
    mma_gemm_kernel<0><<<ggrid, 256>>>(inp, bv, nullptr);

    // 2) sampling locations + softmaxed attention weights (packed g_pts)
    offset_attn_gemm_kernel<<<NROWS / 128, 256>>>(query, refp, Woff, boff, Wa, ba);

    // 3) bilinear sampling + point-weighted sum (issue-optimized)
    sample_kernel<<<(NROWS * 2) / 8, 256>>>();   // 1 warp per (row, 4 heads)

    // 4) out = samp @ Wo^T + bo   (HMMA split-bf16, 2 CTAs/SM)
    mma_gemm_kernel<1><<<ggrid, 256>>>(nullptr, bo, out);
}

// round 16
// speedup vs baseline: 1.1768x; 1.1768x over previous
#include <cuda_runtime.h>
#include <cuda_bf16.h>
#include <cstdint>
#include <math.h>

// Problem constants (fixed by the reference)
#define NB      8
#define LQ      4096
#define DMODEL  256
#define MHEADS  8
#define PPTS    4
#define DH      32
#define HDIM    64
#define WDIM    64
#define NROWS   (NB * LQ)          // 32768
#define NHW     (HDIM * WDIM)      // 4096
#define NOFF    96                 // offset(64) + attn(32) output cols

// ---------------------------------------------------------------------------
// Scratch (device globals; no runtime allocation allowed)
// ---------------------------------------------------------------------------
__device__ float  g_value[NB * NHW * DMODEL];         // 33.5 MB
__device__ float  g_samp [NROWS * DMODEL];            // 33.5 MB
__device__ float  g_locf [NROWS * MHEADS * PPTS * 2]; // pixel coords x,y
__device__ float  g_attw [NROWS * MHEADS * PPTS];     // softmaxed weights
__device__ __nv_bfloat16 g_wv_hi [DMODEL * DMODEL];
__device__ __nv_bfloat16 g_wv_lo [DMODEL * DMODEL];
__device__ __nv_bfloat16 g_wo_hi [DMODEL * DMODEL];
__device__ __nv_bfloat16 g_wo_lo [DMODEL * DMODEL];
__device__ __nv_bfloat16 g_woa_hi[NOFF * DMODEL];     // rows 0-63 Woff, 64-95 Wa
__device__ __nv_bfloat16 g_woa_lo[NOFF * DMODEL];

// ---------------------------------------------------------------------------
// Warp-MMA helpers (sm_80-class PTX; legal on plain sm_100)
// ---------------------------------------------------------------------------
__device__ __forceinline__ uint32_t smem_u32(const void* p) {
    uint32_t a;
    asm("{ .reg .u64 t; cvta.to.shared.u64 t, %1; cvt.u32.u64 %0, t; }"
        : "=r"(a) : "l"(p));
    return a;
}

__device__ __forceinline__ void ldsm4(uint32_t& a, uint32_t& b, uint32_t& c,
                                      uint32_t& d, uint32_t addr) {
    asm volatile("ldmatrix.sync.aligned.m8n8.x4.shared.b16 {%0,%1,%2,%3}, [%4];"
                 : "=r"(a), "=r"(b), "=r"(c), "=r"(d) : "r"(addr));
}

__device__ __forceinline__ void mma_bf16(float* c, const uint32_t* a,
                                         uint32_t b0, uint32_t b1) {
    asm volatile(
        "mma.sync.aligned.m16n8k16.row.col.f32.bf16.bf16.f32 "
        "{%0,%1,%2,%3}, {%4,%5,%6,%7}, {%8,%9}, {%0,%1,%2,%3};"
        : "+f"(c[0]), "+f"(c[1]), "+f"(c[2]), "+f"(c[3])
        : "r"(a[0]), "r"(a[1]), "r"(a[2]), "r"(a[3]), "r"(b0), "r"(b1));
}

// ---------------------------------------------------------------------------
// Weight split: Wv, Wo, and (Woff ‖ Wa) -> (hi, lo) bf16 pairs.
// ---------------------------------------------------------------------------
#define NN_W (DMODEL * DMODEL)          // 65536
#define N_WOFF (64 * DMODEL)            // 16384
#define CONV_TOT (2 * NN_W + NOFF * DMODEL)  // 155648

__global__ __launch_bounds__(256) void conv_weights_kernel(
    const float* __restrict__ Wv, const float* __restrict__ Wo,
    const float* __restrict__ Woff, const float* __restrict__ Wa)
{
    const int i = blockIdx.x * 256 + threadIdx.x;
    if (i >= CONV_TOT) return;
    float v;
    if (i < NN_W)               v = Wv[i];
    else if (i < 2 * NN_W)      v = Wo[i - NN_W];
    else if (i < 2 * NN_W + N_WOFF) v = Woff[i - 2 * NN_W];
    else                        v = Wa[i - 2 * NN_W - N_WOFF];
    __nv_bfloat16 h = __float2bfloat16(v);
    __nv_bfloat16 l = __float2bfloat16(v - __bfloat162float(h));
    if (i < NN_W)          { g_wv_hi[i] = h;            g_wv_lo[i] = l; }
    else if (i < 2 * NN_W) { g_wo_hi[i - NN_W] = h;     g_wo_lo[i - NN_W] = l; }
    else                   { g_woa_hi[i - 2 * NN_W] = h; g_woa_lo[i - 2 * NN_W] = l; }
}

// ---------------------------------------------------------------------------
// HMMA split-bf16 GEMM (byte-identical to the R13 winner).
// Block 128x128, BK=32, 8 warps, __launch_bounds__(256,2) -> 2 CTAs/SM.
// ---------------------------------------------------------------------------
#define BK   32
#define SPAD 40   // bf16 per smem row (80 B; 16B-aligned, conflict-free)

template <int SEL>
__global__ __launch_bounds__(256, 2) void mma_gemm_kernel(
    const float* __restrict__ Aext, const float* __restrict__ bias,
    float* __restrict__ Cext)
{
    __shared__ __nv_bfloat16 Ah[128][SPAD];
    __shared__ __nv_bfloat16 Al[128][SPAD];
    __shared__ __nv_bfloat16 Bh[128][SPAD];
    __shared__ __nv_bfloat16 Bl[128][SPAD];

    const float* A = (SEL == 0) ? Aext : g_samp;
    float*       C = (SEL == 0) ? g_value : Cext;
    const __nv_bfloat16* Wh = (SEL == 0) ? g_wv_hi : g_wo_hi;
    const __nv_bfloat16* Wl = (SEL == 0) ? g_wv_lo : g_wo_lo;

    const int tid  = threadIdx.x;
    const int wid  = tid >> 5;
    const int lane = tid & 31;
    const int m0   = blockIdx.x * 128;
    const int n0   = blockIdx.y * 128;

    const int wm = wid >> 1;
    const int wn = wid & 1;

    const int lrow = tid >> 1;
    const int lkb  = (tid & 1) * 16;

    const float*         Ap  = A  + (size_t)(m0 + lrow) * DMODEL + lkb;
    const __nv_bfloat16* Whp = Wh + (size_t)(n0 + lrow) * DMODEL + lkb;
    const __nv_bfloat16* Wlp = Wl + (size_t)(n0 + lrow) * DMODEL + lkb;

    const int a_row = (lane & 15);
    const int a_k   = (lane >> 4) * 8;
    const int b_g   = lane >> 3;
    const int b_row = (b_g >> 1) * 8 + (lane & 7);
    const int b_k   = (b_g & 1) * 8;

    const uint32_t ah_b = smem_u32(Ah);
    const uint32_t al_b = smem_u32(Al);
    const uint32_t bh_b = smem_u32(Bh);
    const uint32_t bl_b = smem_u32(Bl);

    float acc[2][8][4];
#pragma unroll
    for (int i = 0; i < 2; i++)
#pragma unroll
        for (int j = 0; j < 8; j++)
#pragma unroll
            for (int k = 0; k < 4; k++) acc[i][j][k] = 0.0f;

    for (int k0 = 0; k0 < DMODEL; k0 += BK) {
        if (k0) __syncthreads();

        uint32_t* ah = reinterpret_cast<uint32_t*>(&Ah[lrow][lkb]);
        uint32_t* al = reinterpret_cast<uint32_t*>(&Al[lrow][lkb]);
#pragma unroll
        for (int c = 0; c < 4; c++) {
            float4 v = *reinterpret_cast<const float4*>(Ap + k0 + c * 4);
            __nv_bfloat162 h0 = __floats2bfloat162_rn(v.x, v.y);
            __nv_bfloat162 h1 = __floats2bfloat162_rn(v.z, v.w);
            float2 f0 = __bfloat1622float2(h0);
            float2 f1 = __bfloat1622float2(h1);
            __nv_bfloat162 l0 = __floats2bfloat162_rn(v.x - f0.x, v.y - f0.y);
            __nv_bfloat162 l1 = __floats2bfloat162_rn(v.z - f1.x, v.w - f1.y);
            ah[c * 2 + 0] = *reinterpret_cast<uint32_t*>(&h0);
            ah[c * 2 + 1] = *reinterpret_cast<uint32_t*>(&h1);
            al[c * 2 + 0] = *reinterpret_cast<uint32_t*>(&l0);
            al[c * 2 + 1] = *reinterpret_cast<uint32_t*>(&l1);
        }
        *reinterpret_cast<uint4*>(&Bh[lrow][lkb]) =
            *reinterpret_cast<const uint4*>(Whp + k0);
        *reinterpret_cast<uint4*>(&Bh[lrow][lkb + 8]) =
            *reinterpret_cast<const uint4*>(Whp + k0 + 8);
        *reinterpret_cast<uint4*>(&Bl[lrow][lkb]) =
            *reinterpret_cast<const uint4*>(Wlp + k0);
        *reinterpret_cast<uint4*>(&Bl[lrow][lkb + 8]) =
            *reinterpret_cast<const uint4*>(Wlp + k0 + 8);
        __syncthreads();

#pragma unroll
        for (int ks = 0; ks < 2; ks++) {
            uint32_t ahi[2][4], alo[2][4];
#pragma unroll
            for (int mt = 0; mt < 2; mt++) {
                uint32_t off = ((wm * 32 + mt * 16 + a_row) * SPAD
                                + ks * 16 + a_k) * 2;
                ldsm4(ahi[mt][0], ahi[mt][1], ahi[mt][2], ahi[mt][3], ah_b + off);
                ldsm4(alo[mt][0], alo[mt][1], alo[mt][2], alo[mt][3], al_b + off);
            }
#pragma unroll
            for (int ntp = 0; ntp < 4; ntp++) {
                uint32_t off = ((wn * 64 + ntp * 16 + b_row) * SPAD
                                + ks * 16 + b_k) * 2;
                uint32_t bh0, bh1, bh2, bh3, bl0, bl1, bl2, bl3;
                ldsm4(bh0, bh1, bh2, bh3, bh_b + off);
                ldsm4(bl0, bl1, bl2, bl3, bl_b + off);
#pragma unroll
                for (int mt = 0; mt < 2; mt++) {
                    mma_bf16(acc[mt][ntp * 2 + 0], ahi[mt], bh0, bh1);
                    mma_bf16(acc[mt][ntp * 2 + 1], ahi[mt], bh2, bh3);
                }
#pragma unroll
                for (int mt = 0; mt < 2; mt++) {
                    mma_bf16(acc[mt][ntp * 2 + 0], alo[mt], bh0, bh1);
                    mma_bf16(acc[mt][ntp * 2 + 1], alo[mt], bh2, bh3);
                }
#pragma unroll
                for (int mt = 0; mt < 2; mt++) {
                    mma_bf16(acc[mt][ntp * 2 + 0], ahi[mt], bl0, bl1);
                    mma_bf16(acc[mt][ntp * 2 + 1], ahi[mt], bl2, bl3);
                }
            }
        }
    }

    const int q  = lane >> 2;
    const int rp = (lane & 3) * 2;
#pragma unroll
    for (int mt = 0; mt < 2; mt++) {
        const int r0 = m0 + wm * 32 + mt * 16 + q;
#pragma unroll
        for (int nt = 0; nt < 8; nt++) {
            const int col = n0 + wn * 64 + nt * 8 + rp;
            const float bx = bias[col], by = bias[col + 1];
            float2 o0 = make_float2(acc[mt][nt][0] + bx, acc[mt][nt][1] + by);
            float2 o1 = make_float2(acc[mt][nt][2] + bx, acc[mt][nt][3] + by);
            *reinterpret_cast<float2*>(C + (size_t)r0 * DMODEL + col) = o0;
            *reinterpret_cast<float2*>(C + (size_t)(r0 + 8) * DMODEL + col) = o1;
        }
    }
}

// ---------------------------------------------------------------------------
// Offsets + attention via HMMA: [NROWS x 256] @ [96 x 256]^T.
// Block 128 rows x 96 cols, 8 warps (4M x 2N), warp tile 32x48 (3 n8-pairs).
// Split-bf16 3-product. Logits overlaid on dead mainloop smem; softmax fused.
// Smem: A 20 KB + B 15 KB + refs = ~36.8 KB (safe).
// ---------------------------------------------------------------------------
__global__ __launch_bounds__(256, 2) void offset_attn_mma_kernel(
    const float* __restrict__ query, const float* __restrict__ refpts,
    const float* __restrict__ boff,  const float* __restrict__ ba)
{
    __shared__ union OSMem {
        struct {
            __nv_bfloat16 Ah[128][SPAD];
            __nv_bfloat16 Al[128][SPAD];
            __nv_bfloat16 Bh[NOFF][SPAD];
            __nv_bfloat16 Bl[NOFF][SPAD];
        } mm;                                   // 35.8 KB mainloop
        float logits[128][33];                  // 16.9 KB epilogue overlay
    } sm;
    __shared__ float2 refs[128];

    const int tid  = threadIdx.x;
    const int wid  = tid >> 5;
    const int lane = tid & 31;
    const int m0   = blockIdx.x * 128;

    const int wm = wid >> 1;          // 0..3 -> rows wm*32
    const int wn = wid & 1;           // 0..1 -> cols wn*48

    if (tid < 128) refs[tid] = reinterpret_cast<const float2*>(refpts)[m0 + tid];

    // loaders
    const int lrow = tid >> 1;              // A row 0..127
    const int lkb  = (tid & 1) * 16;
    const float* Ap = query + (size_t)(m0 + lrow) * DMODEL + lkb;
    const int br = tid >> 1;                // B row 0..95 (tid<192)
    const __nv_bfloat16* Whp = g_woa_hi + (size_t)br * DMODEL + lkb;
    const __nv_bfloat16* Wlp = g_woa_lo + (size_t)br * DMODEL + lkb;

    // ldmatrix lane address components
    const int a_row = (lane & 15);
    const int a_k   = (lane >> 4) * 8;
    const int b_g   = lane >> 3;
    const int b_row = (b_g >> 1) * 8 + (lane & 7);
    const int b_k   = (b_g & 1) * 8;

    const uint32_t ah_b = smem_u32(sm.mm.Ah);
    const uint32_t al_b = smem_u32(sm.mm.Al);
    const uint32_t bh_b = smem_u32(sm.mm.Bh);
    const uint32_t bl_b = smem_u32(sm.mm.Bl);

    float acc[2][6][4];
#pragma unroll
    for (int i = 0; i < 2; i++)
#pragma unroll
        for (int j = 0; j < 6; j++)
#pragma unroll
            for (int k = 0; k < 4; k++) acc[i][j][k] = 0.0f;

    for (int k0 = 0; k0 < DMODEL; k0 += BK) {
        if (k0) __syncthreads();

        // stage A: fp32 -> hi/lo bf16
        uint32_t* ah = reinterpret_cast<uint32_t*>(&sm.mm.Ah[lrow][lkb]);
        uint32_t* al = reinterpret_cast<uint32_t*>(&sm.mm.Al[lrow][lkb]);
#pragma unroll
        for (int c = 0; c < 4; c++) {
            float4 v = *reinterpret_cast<const float4*>(Ap + k0 + c * 4);
            __nv_bfloat162 h0 = __floats2bfloat162_rn(v.x, v.y);
            __nv_bfloat162 h1 = __floats2bfloat162_rn(v.z, v.w);
            float2 f0 = __bfloat1622float2(h0);
            float2 f1 = __bfloat1622float2(h1);
            __nv_bfloat162 l0 = __floats2bfloat162_rn(v.x - f0.x, v.y - f0.y);
            __nv_bfloat162 l1 = __floats2bfloat162_rn(v.z - f1.x, v.w - f1.y);
            ah[c * 2 + 0] = *reinterpret_cast<uint32_t*>(&h0);
            ah[c * 2 + 1] = *reinterpret_cast<uint32_t*>(&h1);
            al[c * 2 + 0] = *reinterpret_cast<uint32_t*>(&l0);
            al[c * 2 + 1] = *reinterpret_cast<uint32_t*>(&l1);
        }
        // stage B (96 rows): pre-split bf16, straight copy
        if (tid < 192) {
            *reinterpret_cast<uint4*>(&sm.mm.Bh[br][lkb]) =
                *reinterpret_cast<const uint4*>(Whp + k0);
            *reinterpret_cast<uint4*>(&sm.mm.Bh[br][lkb + 8]) =
                *reinterpret_cast<const uint4*>(Whp + k0 + 8);
            *reinterpret_cast<uint4*>(&sm.mm.Bl[br][lkb]) =
                *reinterpret_cast<const uint4*>(Wlp + k0);
            *reinterpret_cast<uint4*>(&sm.mm.Bl[br][lkb + 8]) =
                *reinterpret_cast<const uint4*>(Wlp + k0 + 8);
        }
        __syncthreads();

#pragma unroll
        for (int ks = 0; ks < 2; ks++) {
            uint32_t ahi[2][4], alo[2][4];
#pragma unroll
            for (int mt = 0; mt < 2; mt++) {
                uint32_t off = ((wm * 32 + mt * 16 + a_row) * SPAD
                                + ks * 16 + a_k) * 2;
                ldsm4(ahi[mt][0], ahi[mt][1], ahi[mt][2], ahi[mt][3], ah_b + off);
                ldsm4(alo[mt][0], alo[mt][1], alo[mt][2], alo[mt][3], al_b + off);
            }
#pragma unroll
            for (int ntp = 0; ntp < 3; ntp++) {
                uint32_t off = ((wn * 48 + ntp * 16 + b_row) * SPAD
                                + ks * 16 + b_k) * 2;
                uint32_t bh0, bh1, bh2, bh3, bl0, bl1, bl2, bl3;
                ldsm4(bh0, bh1, bh2, bh3, bh_b + off);
                ldsm4(bl0, bl1, bl2, bl3, bl_b + off);
#pragma unroll
                for (int mt = 0; mt < 2; mt++) {
                    mma_bf16(acc[mt][ntp * 2 + 0], ahi[mt], bh0, bh1);
                    mma_bf16(acc[mt][ntp * 2 + 1], ahi[mt], bh2, bh3);
                }
#pragma unroll
                for (int mt = 0; mt < 2; mt++) {
                    mma_bf16(acc[mt][ntp * 2 + 0], alo[mt], bh0, bh1);
                    mma_bf16(acc[mt][ntp * 2 + 1], alo[mt], bh2, bh3);
                }
#pragma unroll
                for (int mt = 0; mt < 2; mt++) {
                    mma_bf16(acc[mt][ntp * 2 + 0], ahi[mt], bl0, bl1);
                    mma_bf16(acc[mt][ntp * 2 + 1], ahi[mt], bl2, bl3);
                }
            }
        }
    }
    __syncthreads();   // mainloop smem dead; safe to overlay logits

    // Epilogue: cols<64 -> (x,y) pairs to g_locf; cols>=64 -> logits overlay.
    // Fragment (mt,nt,k): rows q / q+8, cols col / col+1 (col even).
    const int q  = lane >> 2;
    const int rp = (lane & 3) * 2;
#pragma unroll
    for (int mt = 0; mt < 2; mt++) {
#pragma unroll
        for (int nt = 0; nt < 6; nt++) {
            const int col = wn * 48 + nt * 8 + rp;           // even
#pragma unroll
            for (int half = 0; half < 2; half++) {
                const int row  = wm * 32 + mt * 16 + q + half * 8;
                const int grow = m0 + row;
                const float v0 = acc[mt][nt][half * 2 + 0];
                const float v1 = acc[mt][nt][half * 2 + 1];
                if (col < 64) {
                    const float2 r = refs[row];
                    float2 o;
                    o.x = v0 + boff[col]     + r.x * (float)WDIM - 0.5f;
                    o.y = v1 + boff[col + 1] + r.y * (float)HDIM - 0.5f;
                    *reinterpret_cast<float2*>(
                        g_locf + (size_t)grow * 64 + col) = o;
                } else {
                    sm.logits[row][col - 64]     = v0 + ba[col - 64];
                    sm.logits[row][col - 64 + 1] = v1 + ba[col - 64 + 1];
                }
            }
        }
    }
    __syncthreads();

    // softmax over P=4 per (row, head)
    for (int t = tid; t < 128 * MHEADS; t += 256) {
        const int row = t >> 3;
        const int m   = t & 7;
        float l0 = sm.logits[row][m * 4 + 0];
        float l1 = sm.logits[row][m * 4 + 1];
        float l2 = sm.logits[row][m * 4 + 2];
        float l3 = sm.logits[row][m * 4 + 3];
        float mx = fmaxf(fmaxf(l0, l1), fmaxf(l2, l3));
        float e0 = __expf(l0 - mx), e1 = __expf(l1 - mx);
        float e2 = __expf(l2 - mx), e3 = __expf(l3 - mx);
        float inv = 1.0f / (e0 + e1 + e2 + e3);
        const size_t base = (size_t)(m0 + row) * 32 + m * 4;
        g_attw[base + 0] = e0 * inv;
        g_attw[base + 1] = e1 * inv;
        g_attw[base + 2] = e2 * inv;
        g_attw[base + 3] = e3 * inv;
    }
}

// ---------------------------------------------------------------------------
// Bilinear sampling + weighted point sum (byte-identical to R13, 41.4 us):
// 1 warp per (row, 4 heads); lane = (head in group) * 8 + channel-quad.
// ---------------------------------------------------------------------------
__global__ __launch_bounds__(256) void sample_kernel()
{
    const int gwid = (blockIdx.x * blockDim.x + threadIdx.x) >> 5;
    const int lane = threadIdx.x & 31;
    const int row  = gwid >> 1;             // n*LQ + lq
    const int mg   = gwid & 1;              // head group (0: m0-3, 1: m4-7)
    const int m    = mg * 4 + (lane >> 3);  // head
    const int cg   = (lane & 7) * 4;        // channel quad within head
    const int n    = row >> 12;             // LQ = 4096

    const float* vbase = g_value + (size_t)(n * NHW) * DMODEL + m * DH + cg;

    float4 acc = make_float4(0.f, 0.f, 0.f, 0.f);
#pragma unroll
    for (int p = 0; p < PPTS; p++) {
        const int li = row * 32 + m * 4 + p;
        float2 L  = reinterpret_cast<const float2*>(g_locf)[li];
        float  aw = g_attw[li];

        float x0f = floorf(L.x), y0f = floorf(L.y);
        int   x0  = (int)x0f,    y0  = (int)y0f;
        float wx1 = L.x - x0f,   wy1 = L.y - y0f;
        float wx0 = 1.0f - wx1;
        float wy0 = 1.0f - wy1;

        wx0 = (x0 >= 0 && x0 < WDIM)         ? wx0 : 0.0f;
        wx1 = (x0 + 1 >= 0 && x0 + 1 < WDIM) ? wx1 : 0.0f;
        wy0 = ((y0 >= 0 && y0 < HDIM)         ? wy0 : 0.0f) * aw;
        wy1 = ((y0 + 1 >= 0 && y0 + 1 < HDIM) ? wy1 : 0.0f) * aw;

        const int x0c = min(max(x0, 0), WDIM - 1);
        const int x1c = min(max(x0 + 1, 0), WDIM - 1);
        const int y0c = min(max(y0, 0), HDIM - 1);
        const int y1c = min(max(y0 + 1, 0), HDIM - 1);

        const int r0 = y0c * WDIM, r1 = y1c * WDIM;
        float4 v00 = *reinterpret_cast<const float4*>(vbase + (r0 + x0c) * DMODEL);
        float4 v01 = *reinterpret_cast<const float4*>(vbase + (r0 + x1c) * DMODEL);
        float4 v10 = *reinterpret_cast<const float4*>(vbase + (r1 + x0c) * DMODEL);
        float4 v11 = *reinterpret_cast<const float4*>(vbase + (r1 + x1c) * DMODEL);

        const float w00 = wy0 * wx0, w01 = wy0 * wx1;
        const float w10 = wy1 * wx0, w11 = wy1 * wx1;
        acc.x += w00 * v00.x + w01 * v01.x + w10 * v10.x + w11 * v11.x;
        acc.y += w00 * v00.y + w01 * v01.y + w10 * v10.y + w11 * v11.y;
        acc.z += w00 * v00.z + w01 * v01.z + w10 * v10.z + w11 * v11.z;
        acc.w += w00 * v00.w + w01 * v01.w + w10 * v10.w + w11 * v11.w;
    }
    *reinterpret_cast<float4*>(g_samp + (size_t)row * DMODEL + m * DH + cg) = acc;
}

// ---------------------------------------------------------------------------
// Launch — kernel launches only.
// ---------------------------------------------------------------------------
extern "C" void kernel_launch(void* const* d_in, const int* in_sizes, int n_in,
                              void* d_out, int out_size)
{
    const float* query = (const float*)d_in[0];
    const float* refp  = (const float*)d_in[1];
    const float* inp   = (const float*)d_in[2];
    // d_in[3] = H, d_in[4] = W (compile-time constants here)
    const float* Wv    = (const float*)d_in[5];
    const float* bv    = (const float*)d_in[6];
    const float* Woff  = (const float*)d_in[7];
    const float* boff  = (const float*)d_in[8];
    const float* Wa    = (const float*)d_in[9];
    const float* ba    = (const float*)d_in[10];
    const float* Wo    = (const float*)d_in[11];
    const float* bo    = (const float*)d_in[12];
    float* out = (float*)d_out;

    dim3 ggrid(NROWS / 128, DMODEL / 128);   // (256, 2)

    // 0) split all weights to bf16 hi/lo
    conv_weights_kernel<<<(CONV_TOT + 255) / 256, 256>>>(Wv, Wo, Woff, Wa);

    // 1) value = input_flatten @ Wv^T + bv   (HMMA split-bf16, 2 CTAs/SM)
    mma_gemm_kernel<0><<<ggrid, 256>>>(inp, bv, nullptr);

    // 2) sampling locations + softmaxed attention weights (HMMA, N=96)
    offset_attn_mma_kernel<<<NROWS / 128, 256>>>(query, refp, boff, ba);

    // 3) bilinear sampling + point-weighted sum
    sample_kernel<<<(NROWS * 2) / 8, 256>>>();   // 1 warp per (row, 4 heads)

    // 4) out = samp @ Wo^T + bo   (HMMA split-bf16, 2 CTAs/SM)
    mma_gemm_kernel<1><<<ggrid, 256>>>(nullptr, bo, out);
}

// round 17
// speedup vs baseline: 1.1820x; 1.0044x over previous
#include <cuda_runtime.h>
#include <cuda_bf16.h>
#include <cstdint>
#include <math.h>

// Problem constants (fixed by the reference)
#define NB      8
#define LQ      4096
#define DMODEL  256
#define MHEADS  8
#define PPTS    4
#define DH      32
#define HDIM    64
#define WDIM    64
#define NROWS   (NB * LQ)          // 32768
#define NHW     (HDIM * WDIM)      // 4096
#define NOFF    96                 // offset(64) + attn(32) output cols

// ---------------------------------------------------------------------------
// Scratch (device globals; no runtime allocation allowed)
// ---------------------------------------------------------------------------
__device__ float  g_value[NB * NHW * DMODEL];         // 33.5 MB
__device__ float  g_samp [NROWS * DMODEL];            // 33.5 MB
__device__ float  g_locf [NROWS * MHEADS * PPTS * 2]; // pixel coords x,y
__device__ float  g_attw [NROWS * MHEADS * PPTS];     // softmaxed weights
__device__ __nv_bfloat16 g_wv_hi [DMODEL * DMODEL];
__device__ __nv_bfloat16 g_wv_lo [DMODEL * DMODEL];
__device__ __nv_bfloat16 g_wo_hi [DMODEL * DMODEL];
__device__ __nv_bfloat16 g_wo_lo [DMODEL * DMODEL];
__device__ __nv_bfloat16 g_woa_hi[NOFF * DMODEL];     // rows 0-63 Woff, 64-95 Wa
__device__ __nv_bfloat16 g_woa_lo[NOFF * DMODEL];

// ---------------------------------------------------------------------------
// Warp-MMA helpers (sm_80-class PTX; legal on plain sm_100)
// ---------------------------------------------------------------------------
__device__ __forceinline__ uint32_t smem_u32(const void* p) {
    uint32_t a;
    asm("{ .reg .u64 t; cvta.to.shared.u64 t, %1; cvt.u32.u64 %0, t; }"
        : "=r"(a) : "l"(p));
    return a;
}

__device__ __forceinline__ void ldsm4(uint32_t& a, uint32_t& b, uint32_t& c,
                                      uint32_t& d, uint32_t addr) {
    asm volatile("ldmatrix.sync.aligned.m8n8.x4.shared.b16 {%0,%1,%2,%3}, [%4];"
                 : "=r"(a), "=r"(b), "=r"(c), "=r"(d) : "r"(addr));
}

__device__ __forceinline__ void mma_bf16(float* c, const uint32_t* a,
                                         uint32_t b0, uint32_t b1) {
    asm volatile(
        "mma.sync.aligned.m16n8k16.row.col.f32.bf16.bf16.f32 "
        "{%0,%1,%2,%3}, {%4,%5,%6,%7}, {%8,%9}, {%0,%1,%2,%3};"
        : "+f"(c[0]), "+f"(c[1]), "+f"(c[2]), "+f"(c[3])
        : "r"(a[0]), "r"(a[1]), "r"(a[2]), "r"(a[3]), "r"(b0), "r"(b1));
}

// ---------------------------------------------------------------------------
// Weight split: Wv, Wo, and (Woff ‖ Wa) -> (hi, lo) bf16 pairs.
// ---------------------------------------------------------------------------
#define NN_W (DMODEL * DMODEL)          // 65536
#define N_WOFF (64 * DMODEL)            // 16384
#define CONV_TOT (2 * NN_W + NOFF * DMODEL)  // 155648

__global__ __launch_bounds__(256) void conv_weights_kernel(
    const float* __restrict__ Wv, const float* __restrict__ Wo,
    const float* __restrict__ Woff, const float* __restrict__ Wa)
{
    const int i = blockIdx.x * 256 + threadIdx.x;
    if (i >= CONV_TOT) return;
    float v;
    if (i < NN_W)               v = Wv[i];
    else if (i < 2 * NN_W)      v = Wo[i - NN_W];
    else if (i < 2 * NN_W + N_WOFF) v = Woff[i - 2 * NN_W];
    else                        v = Wa[i - 2 * NN_W - N_WOFF];
    __nv_bfloat16 h = __float2bfloat16(v);
    __nv_bfloat16 l = __float2bfloat16(v - __bfloat162float(h));
    if (i < NN_W)          { g_wv_hi[i] = h;            g_wv_lo[i] = l; }
    else if (i < 2 * NN_W) { g_wo_hi[i - NN_W] = h;     g_wo_lo[i - NN_W] = l; }
    else                   { g_woa_hi[i - 2 * NN_W] = h; g_woa_lo[i - 2 * NN_W] = l; }
}

// ---------------------------------------------------------------------------
// Shared-memory layouts
// ---------------------------------------------------------------------------
#define BK   32
#define SPAD 40   // bf16 per smem row (80 B; 16B-aligned, conflict-free)

struct GemmSmem {
    __nv_bfloat16 Ah[128][SPAD];
    __nv_bfloat16 Al[128][SPAD];
    __nv_bfloat16 Bh[128][SPAD];
    __nv_bfloat16 Bl[128][SPAD];
};                                    // 40960 B

struct OffSmem {
    union {
        struct {
            __nv_bfloat16 Ah[128][SPAD];
            __nv_bfloat16 Al[128][SPAD];
            __nv_bfloat16 Bh[NOFF][SPAD];
            __nv_bfloat16 Bl[NOFF][SPAD];
        } mm;                         // 35840 B mainloop
        float logits[128][33];        // 16896 B epilogue overlay
    } u;
    float2 refs[128];                 // 1024 B
};                                    // 36864 B

// ---------------------------------------------------------------------------
// HMMA split-bf16 GEMM body (structure of the R13/R16 winner).
// Block 128x128, BK=32, 8 warps (4M x 2N).
// ---------------------------------------------------------------------------
__device__ __forceinline__ void gemm_body(
    GemmSmem& S,
    const float* __restrict__ A, const __nv_bfloat16* __restrict__ Wh,
    const __nv_bfloat16* __restrict__ Wl, const float* __restrict__ bias,
    float* __restrict__ C, int m0, int n0)
{
    const int tid  = threadIdx.x;
    const int wid  = tid >> 5;
    const int lane = tid & 31;

    const int wm = wid >> 1;
    const int wn = wid & 1;

    const int lrow = tid >> 1;
    const int lkb  = (tid & 1) * 16;

    const float*         Ap  = A  + (size_t)(m0 + lrow) * DMODEL + lkb;
    const __nv_bfloat16* Whp = Wh + (size_t)(n0 + lrow) * DMODEL + lkb;
    const __nv_bfloat16* Wlp = Wl + (size_t)(n0 + lrow) * DMODEL + lkb;

    const int a_row = (lane & 15);
    const int a_k   = (lane >> 4) * 8;
    const int b_g   = lane >> 3;
    const int b_row = (b_g >> 1) * 8 + (lane & 7);
    const int b_k   = (b_g & 1) * 8;

    const uint32_t ah_b = smem_u32(S.Ah);
    const uint32_t al_b = smem_u32(S.Al);
    const uint32_t bh_b = smem_u32(S.Bh);
    const uint32_t bl_b = smem_u32(S.Bl);

    float acc[2][8][4];
#pragma unroll
    for (int i = 0; i < 2; i++)
#pragma unroll
        for (int j = 0; j < 8; j++)
#pragma unroll
            for (int k = 0; k < 4; k++) acc[i][j][k] = 0.0f;

    for (int k0 = 0; k0 < DMODEL; k0 += BK) {
        if (k0) __syncthreads();

        uint32_t* ah = reinterpret_cast<uint32_t*>(&S.Ah[lrow][lkb]);
        uint32_t* al = reinterpret_cast<uint32_t*>(&S.Al[lrow][lkb]);
#pragma unroll
        for (int c = 0; c < 4; c++) {
            float4 v = *reinterpret_cast<const float4*>(Ap + k0 + c * 4);
            __nv_bfloat162 h0 = __floats2bfloat162_rn(v.x, v.y);
            __nv_bfloat162 h1 = __floats2bfloat162_rn(v.z, v.w);
            float2 f0 = __bfloat1622float2(h0);
            float2 f1 = __bfloat1622float2(h1);
            __nv_bfloat162 l0 = __floats2bfloat162_rn(v.x - f0.x, v.y - f0.y);
            __nv_bfloat162 l1 = __floats2bfloat162_rn(v.z - f1.x, v.w - f1.y);
            ah[c * 2 + 0] = *reinterpret_cast<uint32_t*>(&h0);
            ah[c * 2 + 1] = *reinterpret_cast<uint32_t*>(&h1);
            al[c * 2 + 0] = *reinterpret_cast<uint32_t*>(&l0);
            al[c * 2 + 1] = *reinterpret_cast<uint32_t*>(&l1);
        }
        *reinterpret_cast<uint4*>(&S.Bh[lrow][lkb]) =
            *reinterpret_cast<const uint4*>(Whp + k0);
        *reinterpret_cast<uint4*>(&S.Bh[lrow][lkb + 8]) =
            *reinterpret_cast<const uint4*>(Whp + k0 + 8);
        *reinterpret_cast<uint4*>(&S.Bl[lrow][lkb]) =
            *reinterpret_cast<const uint4*>(Wlp + k0);
        *reinterpret_cast<uint4*>(&S.Bl[lrow][lkb + 8]) =
            *reinterpret_cast<const uint4*>(Wlp + k0 + 8);
        __syncthreads();

#pragma unroll
        for (int ks = 0; ks < 2; ks++) {
            uint32_t ahi[2][4], alo[2][4];
#pragma unroll
            for (int mt = 0; mt < 2; mt++) {
                uint32_t off = ((wm * 32 + mt * 16 + a_row) * SPAD
                                + ks * 16 + a_k) * 2;
                ldsm4(ahi[mt][0], ahi[mt][1], ahi[mt][2], ahi[mt][3], ah_b + off);
                ldsm4(alo[mt][0], alo[mt][1], alo[mt][2], alo[mt][3], al_b + off);
            }
#pragma unroll
            for (int ntp = 0; ntp < 4; ntp++) {
                uint32_t off = ((wn * 64 + ntp * 16 + b_row) * SPAD
                                + ks * 16 + b_k) * 2;
                uint32_t bh0, bh1, bh2, bh3, bl0, bl1, bl2, bl3;
                ldsm4(bh0, bh1, bh2, bh3, bh_b + off);
                ldsm4(bl0, bl1, bl2, bl3, bl_b + off);
#pragma unroll
                for (int mt = 0; mt < 2; mt++) {
                    mma_bf16(acc[mt][ntp * 2 + 0], ahi[mt], bh0, bh1);
                    mma_bf16(acc[mt][ntp * 2 + 1], ahi[mt], bh2, bh3);
                }
#pragma unroll
                for (int mt = 0; mt < 2; mt++) {
                    mma_bf16(acc[mt][ntp * 2 + 0], alo[mt], bh0, bh1);
                    mma_bf16(acc[mt][ntp * 2 + 1], alo[mt], bh2, bh3);
                }
#pragma unroll
                for (int mt = 0; mt < 2; mt++) {
                    mma_bf16(acc[mt][ntp * 2 + 0], ahi[mt], bl0, bl1);
                    mma_bf16(acc[mt][ntp * 2 + 1], ahi[mt], bl2, bl3);
                }
            }
        }
    }

    const int q  = lane >> 2;
    const int rp = (lane & 3) * 2;
#pragma unroll
    for (int mt = 0; mt < 2; mt++) {
        const int r0 = m0 + wm * 32 + mt * 16 + q;
#pragma unroll
        for (int nt = 0; nt < 8; nt++) {
            const int col = n0 + wn * 64 + nt * 8 + rp;
            const float bx = bias[col], by = bias[col + 1];
            float2 o0 = make_float2(acc[mt][nt][0] + bx, acc[mt][nt][1] + by);
            float2 o1 = make_float2(acc[mt][nt][2] + bx, acc[mt][nt][3] + by);
            *reinterpret_cast<float2*>(C + (size_t)r0 * DMODEL + col) = o0;
            *reinterpret_cast<float2*>(C + (size_t)(r0 + 8) * DMODEL + col) = o1;
        }
    }
}

// ---------------------------------------------------------------------------
// Offsets + attention HMMA body (structure of the R16 winner).
// Block 128 rows x 96 cols, 8 warps (4M x 2N), warp tile 32x48.
// ---------------------------------------------------------------------------
__device__ __forceinline__ void offset_mma_body(
    OffSmem& S,
    const float* __restrict__ query, const float* __restrict__ refpts,
    const float* __restrict__ boff,  const float* __restrict__ ba, int m0)
{
    const int tid  = threadIdx.x;
    const int wid  = tid >> 5;
    const int lane = tid & 31;

    const int wm = wid >> 1;          // 0..3 -> rows wm*32
    const int wn = wid & 1;           // 0..1 -> cols wn*48

    if (tid < 128) S.refs[tid] = reinterpret_cast<const float2*>(refpts)[m0 + tid];

    const int lrow = tid >> 1;
    const int lkb  = (tid & 1) * 16;
    const float* Ap = query + (size_t)(m0 + lrow) * DMODEL + lkb;
    const int br = tid >> 1;
    const __nv_bfloat16* Whp = g_woa_hi + (size_t)br * DMODEL + lkb;
    const __nv_bfloat16* Wlp = g_woa_lo + (size_t)br * DMODEL + lkb;

    const int a_row = (lane & 15);
    const int a_k   = (lane >> 4) * 8;
    const int b_g   = lane >> 3;
    const int b_row = (b_g >> 1) * 8 + (lane & 7);
    const int b_k   = (b_g & 1) * 8;

    const uint32_t ah_b = smem_u32(S.u.mm.Ah);
    const uint32_t al_b = smem_u32(S.u.mm.Al);
    const uint32_t bh_b = smem_u32(S.u.mm.Bh);
    const uint32_t bl_b = smem_u32(S.u.mm.Bl);

    float acc[2][6][4];
#pragma unroll
    for (int i = 0; i < 2; i++)
#pragma unroll
        for (int j = 0; j < 6; j++)
#pragma unroll
            for (int k = 0; k < 4; k++) acc[i][j][k] = 0.0f;

    for (int k0 = 0; k0 < DMODEL; k0 += BK) {
        if (k0) __syncthreads();

        uint32_t* ah = reinterpret_cast<uint32_t*>(&S.u.mm.Ah[lrow][lkb]);
        uint32_t* al = reinterpret_cast<uint32_t*>(&S.u.mm.Al[lrow][lkb]);
#pragma unroll
        for (int c = 0; c < 4; c++) {
            float4 v = *reinterpret_cast<const float4*>(Ap + k0 + c * 4);
            __nv_bfloat162 h0 = __floats2bfloat162_rn(v.x, v.y);
            __nv_bfloat162 h1 = __floats2bfloat162_rn(v.z, v.w);
            float2 f0 = __bfloat1622float2(h0);
            float2 f1 = __bfloat1622float2(h1);
            __nv_bfloat162 l0 = __floats2bfloat162_rn(v.x - f0.x, v.y - f0.y);
            __nv_bfloat162 l1 = __floats2bfloat162_rn(v.z - f1.x, v.w - f1.y);
            ah[c * 2 + 0] = *reinterpret_cast<uint32_t*>(&h0);
            ah[c * 2 + 1] = *reinterpret_cast<uint32_t*>(&h1);
            al[c * 2 + 0] = *reinterpret_cast<uint32_t*>(&l0);
            al[c * 2 + 1] = *reinterpret_cast<uint32_t*>(&l1);
        }
        if (tid < 192) {
            *reinterpret_cast<uint4*>(&S.u.mm.Bh[br][lkb]) =
                *reinterpret_cast<const uint4*>(Whp + k0);
            *reinterpret_cast<uint4*>(&S.u.mm.Bh[br][lkb + 8]) =
                *reinterpret_cast<const uint4*>(Whp + k0 + 8);
            *reinterpret_cast<uint4*>(&S.u.mm.Bl[br][lkb]) =
                *reinterpret_cast<const uint4*>(Wlp + k0);
            *reinterpret_cast<uint4*>(&S.u.mm.Bl[br][lkb + 8]) =
                *reinterpret_cast<const uint4*>(Wlp + k0 + 8);
        }
        __syncthreads();

#pragma unroll
        for (int ks = 0; ks < 2; ks++) {
            uint32_t ahi[2][4], alo[2][4];
#pragma unroll
            for (int mt = 0; mt < 2; mt++) {
                uint32_t off = ((wm * 32 + mt * 16 + a_row) * SPAD
                                + ks * 16 + a_k) * 2;
                ldsm4(ahi[mt][0], ahi[mt][1], ahi[mt][2], ahi[mt][3], ah_b + off);
                ldsm4(alo[mt][0], alo[mt][1], alo[mt][2], alo[mt][3], al_b + off);
            }
#pragma unroll
            for (int ntp = 0; ntp < 3; ntp++) {
                uint32_t off = ((wn * 48 + ntp * 16 + b_row) * SPAD
                                + ks * 16 + b_k) * 2;
                uint32_t bh0, bh1, bh2, bh3, bl0, bl1, bl2, bl3;
                ldsm4(bh0, bh1, bh2, bh3, bh_b + off);
                ldsm4(bl0, bl1, bl2, bl3, bl_b + off);
#pragma unroll
                for (int mt = 0; mt < 2; mt++) {
                    mma_bf16(acc[mt][ntp * 2 + 0], ahi[mt], bh0, bh1);
                    mma_bf16(acc[mt][ntp * 2 + 1], ahi[mt], bh2, bh3);
                }
#pragma unroll
                for (int mt = 0; mt < 2; mt++) {
                    mma_bf16(acc[mt][ntp * 2 + 0], alo[mt], bh0, bh1);
                    mma_bf16(acc[mt][ntp * 2 + 1], alo[mt], bh2, bh3);
                }
#pragma unroll
                for (int mt = 0; mt < 2; mt++) {
                    mma_bf16(acc[mt][ntp * 2 + 0], ahi[mt], bl0, bl1);
                    mma_bf16(acc[mt][ntp * 2 + 1], ahi[mt], bl2, bl3);
                }
            }
        }
    }
    __syncthreads();   // mainloop smem dead; safe to overlay logits

    const int q  = lane >> 2;
    const int rp = (lane & 3) * 2;
#pragma unroll
    for (int mt = 0; mt < 2; mt++) {
#pragma unroll
        for (int nt = 0; nt < 6; nt++) {
            const int col = wn * 48 + nt * 8 + rp;           // even
#pragma unroll
            for (int half = 0; half < 2; half++) {
                const int row  = wm * 32 + mt * 16 + q + half * 8;
                const int grow = m0 + row;
                const float v0 = acc[mt][nt][half * 2 + 0];
                const float v1 = acc[mt][nt][half * 2 + 1];
                if (col < 64) {
                    const float2 r = S.refs[row];
                    float2 o;
                    o.x = v0 + boff[col]     + r.x * (float)WDIM - 0.5f;
                    o.y = v1 + boff[col + 1] + r.y * (float)HDIM - 0.5f;
                    *reinterpret_cast<float2*>(
                        g_locf + (size_t)grow * 64 + col) = o;
                } else {
                    S.u.logits[row][col - 64]     = v0 + ba[col - 64];
                    S.u.logits[row][col - 64 + 1] = v1 + ba[col - 64 + 1];
                }
            }
        }
    }
    __syncthreads();

    for (int t = tid; t < 128 * MHEADS; t += 256) {
        const int row = t >> 3;
        const int m   = t & 7;
        float l0 = S.u.logits[row][m * 4 + 0];
        float l1 = S.u.logits[row][m * 4 + 1];
        float l2 = S.u.logits[row][m * 4 + 2];
        float l3 = S.u.logits[row][m * 4 + 3];
        float mx = fmaxf(fmaxf(l0, l1), fmaxf(l2, l3));
        float e0 = __expf(l0 - mx), e1 = __expf(l1 - mx);
        float e2 = __expf(l2 - mx), e3 = __expf(l3 - mx);
        float inv = 1.0f / (e0 + e1 + e2 + e3);
        const size_t base = (size_t)(m0 + row) * 32 + m * 4;
        g_attw[base + 0] = e0 * inv;
        g_attw[base + 1] = e1 * inv;
        g_attw[base + 2] = e2 * inv;
        g_attw[base + 3] = e3 * inv;
    }
}

// ---------------------------------------------------------------------------
// Fused stage 1+2: value GEMM (blockIdx.y 0/1) runs concurrently with the
// HMMA offset/attn (blockIdx.y == 2). __launch_bounds__(256,2) fixes the
// R12 occupancy failure (135 regs -> 1 CTA/SM); smem union 41 KB x2 = 82 KB.
// ---------------------------------------------------------------------------
__global__ __launch_bounds__(256, 2) void fused_val_off_kernel(
    const float* __restrict__ inp,   const float* __restrict__ bv,
    const float* __restrict__ query, const float* __restrict__ refp,
    const float* __restrict__ boff,  const float* __restrict__ ba)
{
    __shared__ union { GemmSmem g; OffSmem o; } sm;
    if (blockIdx.y < 2) {
        gemm_body(sm.g, inp, g_wv_hi, g_wv_lo, bv, g_value,
                  blockIdx.x * 128, blockIdx.y * 128);
    } else {
        offset_mma_body(sm.o, query, refp, boff, ba, blockIdx.x * 128);
    }
}

// ---------------------------------------------------------------------------
// Stage 4: output projection GEMM (standalone, 2 CTAs/SM)
// ---------------------------------------------------------------------------
__global__ __launch_bounds__(256, 2) void out_gemm_kernel(
    const float* __restrict__ bias, float* __restrict__ C)
{
    __shared__ GemmSmem S;
    gemm_body(S, g_samp, g_wo_hi, g_wo_lo, bias, C,
              blockIdx.x * 128, blockIdx.y * 128);
}

// ---------------------------------------------------------------------------
// Bilinear sampling + weighted point sum (byte-identical to R13/R16, 41.4 us)
// ---------------------------------------------------------------------------
__global__ __launch_bounds__(256) void sample_kernel()
{
    const int gwid = (blockIdx.x * blockDim.x + threadIdx.x) >> 5;
    const int lane = threadIdx.x & 31;
    const int row  = gwid >> 1;             // n*LQ + lq
    const int mg   = gwid & 1;              // head group (0: m0-3, 1: m4-7)
    const int m    = mg * 4 + (lane >> 3);  // head
    const int cg   = (lane & 7) * 4;        // channel quad within head
    const int n    = row >> 12;             // LQ = 4096

    const float* vbase = g_value + (size_t)(n * NHW) * DMODEL + m * DH + cg;

    float4 acc = make_float4(0.f, 0.f, 0.f, 0.f);
#pragma unroll
    for (int p = 0; p < PPTS; p++) {
        const int li = row * 32 + m * 4 + p;
        float2 L  = reinterpret_cast<const float2*>(g_locf)[li];
        float  aw = g_attw[li];

        float x0f = floorf(L.x), y0f = floorf(L.y);
        int   x0  = (int)x0f,    y0  = (int)y0f;
        float wx1 = L.x - x0f,   wy1 = L.y - y0f;
        float wx0 = 1.0f - wx1;
        float wy0 = 1.0f - wy1;

        wx0 = (x0 >= 0 && x0 < WDIM)         ? wx0 : 0.0f;
        wx1 = (x0 + 1 >= 0 && x0 + 1 < WDIM) ? wx1 : 0.0f;
        wy0 = ((y0 >= 0 && y0 < HDIM)         ? wy0 : 0.0f) * aw;
        wy1 = ((y0 + 1 >= 0 && y0 + 1 < HDIM) ? wy1 : 0.0f) * aw;

        const int x0c = min(max(x0, 0), WDIM - 1);
        const int x1c = min(max(x0 + 1, 0), WDIM - 1);
        const int y0c = min(max(y0, 0), HDIM - 1);
        const int y1c = min(max(y0 + 1, 0), HDIM - 1);

        const int r0 = y0c * WDIM, r1 = y1c * WDIM;
        float4 v00 = *reinterpret_cast<const float4*>(vbase + (r0 + x0c) * DMODEL);
        float4 v01 = *reinterpret_cast<const float4*>(vbase + (r0 + x1c) * DMODEL);
        float4 v10 = *reinterpret_cast<const float4*>(vbase + (r1 + x0c) * DMODEL);
        float4 v11 = *reinterpret_cast<const float4*>(vbase + (r1 + x1c) * DMODEL);

        const float w00 = wy0 * wx0, w01 = wy0 * wx1;
        const float w10 = wy1 * wx0, w11 = wy1 * wx1;
        acc.x += w00 * v00.x + w01 * v01.x + w10 * v10.x + w11 * v11.x;
        acc.y += w00 * v00.y + w01 * v01.y + w10 * v10.y + w11 * v11.y;
        acc.z += w00 * v00.z + w01 * v01.z + w10 * v10.z + w11 * v11.z;
        acc.w += w00 * v00.w + w01 * v01.w + w10 * v10.w + w11 * v11.w;
    }
    *reinterpret_cast<float4*>(g_samp + (size_t)row * DMODEL + m * DH + cg) = acc;
}

// ---------------------------------------------------------------------------
// Launch — kernel launches only.
// ---------------------------------------------------------------------------
extern "C" void kernel_launch(void* const* d_in, const int* in_sizes, int n_in,
                              void* d_out, int out_size)
{
    const float* query = (const float*)d_in[0];
    const float* refp  = (const float*)d_in[1];
    const float* inp   = (const float*)d_in[2];
    // d_in[3] = H, d_in[4] = W (compile-time constants here)
    const float* Wv    = (const float*)d_in[5];
    const float* bv    = (const float*)d_in[6];
    const float* Woff  = (const float*)d_in[7];
    const float* boff  = (const float*)d_in[8];
    const float* Wa    = (const float*)d_in[9];
    const float* ba    = (const float*)d_in[10];
    const float* Wo    = (const float*)d_in[11];
    const float* bo    = (const float*)d_in[12];
    float* out = (float*)d_out;

    // 0) split all weights to bf16 hi/lo
    conv_weights_kernel<<<(CONV_TOT + 255) / 256, 256>>>(Wv, Wo, Woff, Wa);

    // 1+2) value GEMM || offset/attn (one grid; y=0,1 gemm halves, y=2 offset)
    dim3 fgrid(NROWS / 128, 3);   // (256, 3)
    fused_val_off_kernel<<<fgrid, 256>>>(inp, bv, query, refp, boff, ba);

    // 3) bilinear sampling + point-weighted sum
    sample_kernel<<<(NROWS * 2) / 8, 256>>>();   // 1 warp per (row, 4 heads)

    // 4) out = samp @ Wo^T + bo
    dim3 ggrid(NROWS / 128, DMODEL / 128);   // (256, 2)
    out_gemm_kernel<<<ggrid, 256>>>(bo, out);
}